// round 5
// baseline (speedup 1.0000x reference)
#include <cuda_runtime.h>
#include <cuda_bf16.h>
#include <cstdint>

#define BATCH 8
#define CDIM  64
#define NPTS  4096
#define KNBR  16
#define COUT  64
#define KSUP  32          // approximate superset size per row
#define NC    128         // candidates per tile in phase B
#define NTIL  (NPTS / NC) // 32

typedef unsigned long long ull;

// ---------------- scratch (no allocations allowed) ----------------
__device__ float          g_sq  [BATCH * NPTS];
__device__ int            g_idx [BATCH * NPTS * KNBR];
__device__ float          g_A   [BATCH * NPTS * COUT];
__device__ float          g_Cp  [BATCH * NPTS * COUT];
__device__ float          g_xt  [BATCH * NPTS * CDIM];   // point-major fp32
__device__ __nv_bfloat16  g_xh  [BATCH * NPTS * CDIM];   // point-major bf16
__device__ short          g_cand[BATCH * NPTS * KSUP];

// ---------------- helpers ----------------
__device__ __forceinline__ uint32_t smem_u32(const void* p) {
    uint32_t a;
    asm("{ .reg .u64 t; cvta.to.shared.u64 t, %1; cvt.u32.u64 %0, t; }" : "=r"(a) : "l"(p));
    return a;
}
__device__ __forceinline__ unsigned fsort(float v) {
    unsigned u = __float_as_uint(v);
    return u ^ (0x80000000u | (unsigned)((int)u >> 31));
}
__device__ __forceinline__ float funsort(unsigned s) {
    unsigned u = (s & 0x80000000u) ? (s ^ 0x80000000u) : ~s;
    return __uint_as_float(u);
}
__device__ __forceinline__ void ldmx4(uint32_t* r, uint32_t addr) {
    asm volatile("ldmatrix.sync.aligned.m8n8.x4.shared.b16 {%0,%1,%2,%3}, [%4];"
                 : "=r"(r[0]), "=r"(r[1]), "=r"(r[2]), "=r"(r[3]) : "r"(addr));
}
__device__ __forceinline__ void mma16816(float* c, const uint32_t* a, uint32_t b0, uint32_t b1) {
    asm volatile("mma.sync.aligned.m16n8k16.row.col.f32.bf16.bf16.f32 "
                 "{%0,%1,%2,%3}, {%4,%5,%6,%7}, {%8,%9}, {%0,%1,%2,%3};"
                 : "+f"(c[0]), "+f"(c[1]), "+f"(c[2]), "+f"(c[3])
                 : "r"(a[0]), "r"(a[1]), "r"(a[2]), "r"(a[3]), "r"(b0), "r"(b1));
}
// swizzled byte offset of 16B granule g (0..7) in row rr of a [rows][64bf16] tile
__device__ __forceinline__ int swz(int rr, int g) {
    return rr * 128 + ((g ^ (rr & 7)) << 4);
}

// ---------------- kernel 1: squared norms (exact fp32) ----------------
__global__ void sq_kernel(const float* __restrict__ x) {
    int b = blockIdx.y;
    int n = blockIdx.x * blockDim.x + threadIdx.x;
    const float* xp = x + (size_t)b * CDIM * NPTS + n;
    float s = 0.f;
#pragma unroll
    for (int c = 0; c < CDIM; ++c) { float v = xp[c * NPTS]; s = fmaf(v, v, s); }
    g_sq[b * NPTS + n] = s;
}

// ---------------- kernel 1b: transpose to point-major fp32 + bf16 ----------------
__global__ void tr_kernel(const float* __restrict__ x) {
    __shared__ float tile[32][33];
    const int tx = threadIdx.x, ty = threadIdx.y;
    const int n0 = blockIdx.x * 32, c0 = blockIdx.y * 32, b = blockIdx.z;
    const float* xb = x + (size_t)b * CDIM * NPTS;
#pragma unroll
    for (int i = 0; i < 4; ++i)
        tile[ty + i * 8][tx] = xb[(c0 + ty + i * 8) * NPTS + n0 + tx];
    __syncthreads();
#pragma unroll
    for (int i = 0; i < 4; ++i) {
        int n = n0 + ty + i * 8, c = c0 + tx;
        float v = tile[tx][ty + i * 8];
        size_t o = ((size_t)b * NPTS + n) * CDIM + c;
        g_xt[o] = v;
        g_xh[o] = __float2bfloat16(v);
    }
}

// ---------------- kernel 2: HMMA approx distances + top-32 superset ----------------
#define PSTR   129
#define SM_A   0
#define SM_B0  16384
#define SM_B1  32768
#define SM_SQS 49152
#define SM_PEND (SM_SQS + NPTS * 4)                 // ull[128][129]
#define SM_THR  (SM_PEND + 128 * PSTR * 8)
#define SM_CNT  (SM_THR + 128 * 4)
#define KNN_SMEM (SM_CNT + 128 * 4)

__global__ __launch_bounds__(256, 1) void knn_mma_kernel() {
    extern __shared__ char sm[];
    float* sqs  = (float*)(sm + SM_SQS);
    ull*   pend = (ull*)  (sm + SM_PEND);
    float* thr  = (float*)(sm + SM_THR);
    int*   cnt  = (int*)  (sm + SM_CNT);

    const int tid  = threadIdx.x;
    const int w    = tid >> 5;
    const int lane = tid & 31;
    const int b    = blockIdx.y;
    const int row0 = blockIdx.x * 128;
    const uint32_t smb = smem_u32(sm);

    const __nv_bfloat16* gb = g_xh + (size_t)b * NPTS * CDIM;

    // prologue: A tile (swizzled), B tile 0, sqs, thr/cnt
#pragma unroll
    for (int i = 0; i < 4; ++i) {
        int q = tid + i * 256, rr = q >> 3, g = q & 7;
        *(uint4*)(sm + SM_A + swz(rr, g))  = *(const uint4*)(gb + (size_t)(row0 + rr) * CDIM + g * 8);
        *(uint4*)(sm + SM_B0 + swz(rr, g)) = *(const uint4*)(gb + (size_t)rr * CDIM + g * 8);
        *(float4*)(sqs + q * 4)            = *(const float4*)(g_sq + (size_t)b * NPTS + q * 4);
    }
    if (tid < 128) { thr[tid] = 3.4e38f; cnt[tid] = 0; }
    __syncthreads();

    // per-warp: rows wrow..wrow+15; owner lanes (even) own one local row each
    const int  wrow  = w * 16;
    const bool owner = (lane & 1) == 0;
    const int  lrow  = wrow + (lane >> 1);       // valid when owner

    ull list[KSUP]; ull worst = ~0ULL; int wpos = 0;
#pragma unroll
    for (int s = 0; s < KSUP; ++s) list[s] = ~0ULL;

    const int arow = wrow + (lane & 7) + ((lane >> 3) & 1) * 8;
    const int rA   = wrow + (lane >> 2);
    const int rB   = rA + 8;

    for (int t = 0; t < NTIL; ++t) {
        const uint32_t bbase = smb + ((t & 1) ? SM_B1 : SM_B0);
        // A fragments (4 k-chunks of k16)
        uint32_t af[4][4];
#pragma unroll
        for (int kc = 0; kc < 4; ++kc) {
            int ach = kc * 2 + (lane >> 4);
            ldmx4(af[kc], smb + SM_A + swz(arow, ach));
        }
        float acc[16][4];
#pragma unroll
        for (int nf = 0; nf < 16; ++nf) {
            acc[nf][0] = acc[nf][1] = acc[nf][2] = acc[nf][3] = 0.f;
            // B fragments: NON-trans ldmatrix on [n][k] row-major tiles.
            // x4 matrices = k-granules; lane L: row nf*8+(L&7), granule L>>3 (+4)
            int brow = nf * 8 + (lane & 7);
            int bg   = lane >> 3;
            uint32_t p[4], q4[4];
            ldmx4(p,  bbase + swz(brow, bg));       // granules 0-3 (k 0..31)
            ldmx4(q4, bbase + swz(brow, bg + 4));   // granules 4-7 (k 32..63)
            mma16816(acc[nf], af[0], p[0],  p[1]);
            mma16816(acc[nf], af[1], p[2],  p[3]);
            mma16816(acc[nf], af[2], q4[0], q4[1]);
            mma16816(acc[nf], af[3], q4[2], q4[3]);
        }
        // prefetch next B tile
        if (t + 1 < NTIL) {
            char* dst = sm + (((t + 1) & 1) ? SM_B1 : SM_B0);
            const __nv_bfloat16* src = gb + (size_t)(t + 1) * NC * CDIM;
#pragma unroll
            for (int i = 0; i < 4; ++i) {
                int q = tid + i * 256, rr = q >> 3, g = q & 7;
                *(uint4*)(dst + swz(rr, g)) = *(const uint4*)(src + (size_t)rr * CDIM + g * 8);
            }
        }
        // epilogue: threshold test + append (warp-private rows)
        {
            float thrA = thr[rA], thrB = thr[rB];
            const int mb = t * NC + (lane & 3) * 2;
#pragma unroll
            for (int nf = 0; nf < 16; ++nf) {
                int   m0 = mb + nf * 8;
                float s0 = sqs[m0], s1 = sqs[m0 + 1];
                float v00 = fmaf(-2.f, acc[nf][0], s0);
                float v01 = fmaf(-2.f, acc[nf][1], s1);
                float v10 = fmaf(-2.f, acc[nf][2], s0);
                float v11 = fmaf(-2.f, acc[nf][3], s1);
                if (v00 <= thrA) { int p = atomicAdd(&cnt[rA], 1);
                    pend[rA * PSTR + p] = ((ull)fsort(v00) << 32) | (unsigned)m0; }
                if (v01 <= thrA) { int p = atomicAdd(&cnt[rA], 1);
                    pend[rA * PSTR + p] = ((ull)fsort(v01) << 32) | (unsigned)(m0 + 1); }
                if (v10 <= thrB) { int p = atomicAdd(&cnt[rB], 1);
                    pend[rB * PSTR + p] = ((ull)fsort(v10) << 32) | (unsigned)m0; }
                if (v11 <= thrB) { int p = atomicAdd(&cnt[rB], 1);
                    pend[rB * PSTR + p] = ((ull)fsort(v11) << 32) | (unsigned)(m0 + 1); }
            }
        }
        __syncwarp();   // appends are warp-private: warp barrier suffices
        // flush pendings into register top-32 (owner lanes)
        {
            unsigned myc  = owner ? (unsigned)cnt[lrow] : 0u;
            unsigned cmax = __reduce_max_sync(0xffffffffu, myc);
            for (unsigned j = 0; j < cmax; ++j) {
                ull key = (j < myc) ? pend[lrow * PSTR + j] : ~0ULL;
                bool take = key < worst;
                if (__any_sync(0xffffffffu, take)) {
#pragma unroll
                    for (int s = 0; s < KSUP; ++s)
                        if (take && s == wpos) list[s] = key;
                    ull wv = list[0]; int p = 0;
#pragma unroll
                    for (int s = 1; s < KSUP; ++s)
                        if (list[s] > wv) { wv = list[s]; p = s; }
                    worst = wv; wpos = p;
                }
            }
            if (owner) {
                thr[lrow] = funsort((unsigned)(worst >> 32));
                cnt[lrow] = 0;
            }
        }
        __syncthreads();  // orders B prefetch for next tile + thr updates
    }

    if (owner) {
        short* op = g_cand + ((size_t)b * NPTS + row0 + lrow) * KSUP;
#pragma unroll
        for (int k = 0; k < KSUP; ++k) op[k] = (short)(list[k] & 0xFFFFu);
    }
}

// ---------------- kernel 2b: exact rescore of 32 candidates, top-16 ----------------
__global__ __launch_bounds__(128, 8) void rescore_kernel() {
    __shared__ float xrow[4][CDIM];
    const int lane = threadIdx.x & 31;
    const int w    = threadIdx.x >> 5;
    const int b    = blockIdx.y;
    const int n    = blockIdx.x * 4 + w;
    const size_t rb = (size_t)b * NPTS + n;

    // stage own row
    *(float2*)(&xrow[w][lane * 2]) = *(const float2*)(g_xt + rb * CDIM + lane * 2);
    __syncwarp();

    int j = (int)g_cand[rb * KSUP + lane];
    ull key;
    if (j == n) {
        key = ~0ULL;
    } else {
        const float* yp = g_xt + ((size_t)b * NPTS + j) * CDIM;
        float dot = 0.f;
#pragma unroll
        for (int c = 0; c < CDIM / 4; ++c) {
            float4 yv = *(const float4*)(yp + c * 4);
            float4 xv = *(const float4*)(&xrow[w][c * 4]);
            dot = fmaf(xv.x, yv.x, dot);
            dot = fmaf(xv.y, yv.y, dot);
            dot = fmaf(xv.z, yv.z, dot);
            dot = fmaf(xv.w, yv.w, dot);
        }
        float dist = fmaf(-2.f, dot, g_sq[(size_t)b * NPTS + j]);
        key = ((ull)fsort(dist) << 32) | (unsigned)j;
    }
    // 32-lane bitonic sort (ascending)
#pragma unroll
    for (int k = 2; k <= 32; k <<= 1) {
#pragma unroll
        for (int jj = k >> 1; jj > 0; jj >>= 1) {
            ull other = __shfl_xor_sync(0xffffffffu, key, jj);
            bool up   = ((lane & k) == 0);
            bool low  = ((lane & jj) == 0);
            bool keep_small = (low == up);
            ull mn = key < other ? key : other;
            ull mx = key < other ? other : key;
            key = keep_small ? mn : mx;
        }
    }
    if (lane < KNBR)
        g_idx[rb * KNBR + lane] = (int)(key & 0xFFFFu);
}

// ---------------- kernel 3: A = W1.x ; Cpre = (W2-W1).x + b1+b2 ----------------
__global__ void feat_kernel(const float* __restrict__ x,
                            const float* __restrict__ W1, const float* __restrict__ b1,
                            const float* __restrict__ W2, const float* __restrict__ b2) {
    __shared__ float xs [CDIM][64];
    __shared__ float w1s[COUT][CDIM];
    __shared__ float wds[COUT][CDIM];
    __shared__ float bs [COUT];

    const int tid = threadIdx.x;
    const int b   = blockIdx.y;
    const int n0  = blockIdx.x * 64;
    const float* xb = x + (size_t)b * CDIM * NPTS;

#pragma unroll
    for (int i = 0; i < 4; ++i) {
        int q = tid + i * 256, c = q >> 4, mg = q & 15;
        *(float4*)(&xs[c][mg * 4]) = *(const float4*)(xb + c * NPTS + n0 + mg * 4);
    }
#pragma unroll
    for (int i = 0; i < 4; ++i) {
        int q = tid + i * 256, o = q >> 4, cg = (q & 15) * 4;
        float4 w1v = *(const float4*)(W1 + o * CDIM + cg);
        float4 w2v = *(const float4*)(W2 + o * CDIM + cg);
        *(float4*)(&w1s[o][cg]) = w1v;
        *(float4*)(&wds[o][cg]) = make_float4(w2v.x - w1v.x, w2v.y - w1v.y,
                                              w2v.z - w1v.z, w2v.w - w1v.w);
    }
    if (tid < COUT) bs[tid] = b1[tid] + b2[tid];
    __syncthreads();

    const int tx = tid & 15;
    const int ty = tid >> 4;
    float aA[4][4] = {}, aC[4][4] = {};
#pragma unroll 16
    for (int c = 0; c < CDIM; ++c) {
        float4 xv = *(const float4*)(&xs[c][tx * 4]);
        float xr[4] = { xv.x, xv.y, xv.z, xv.w };
#pragma unroll
        for (int jj = 0; jj < 4; ++jj) {
            float w1e = w1s[ty * 4 + jj][c];
            float wde = wds[ty * 4 + jj][c];
#pragma unroll
            for (int i = 0; i < 4; ++i) {
                aA[i][jj] = fmaf(xr[i], w1e, aA[i][jj]);
                aC[i][jj] = fmaf(xr[i], wde, aC[i][jj]);
            }
        }
    }
#pragma unroll
    for (int i = 0; i < 4; ++i) {
        int n = n0 + tx * 4 + i;
        float* ap = g_A  + ((size_t)b * NPTS + n) * COUT + ty * 4;
        float* cp = g_Cp + ((size_t)b * NPTS + n) * COUT + ty * 4;
        *(float4*)ap = make_float4(aA[i][0], aA[i][1], aA[i][2], aA[i][3]);
        *(float4*)cp = make_float4(aC[i][0] + bs[ty * 4 + 0],
                                   aC[i][1] + bs[ty * 4 + 1],
                                   aC[i][2] + bs[ty * 4 + 2],
                                   aC[i][3] + bs[ty * 4 + 3]);
    }
}

// ---------------- kernel 4: gather-max + relu ----------------
__global__ void gather_kernel(float* __restrict__ out) {
    const int tid = threadIdx.x;
    const int b   = blockIdx.y;
    const int n   = blockIdx.x * 64 + (tid & 63);
    const int g   = tid >> 6;
    const int* ip = g_idx + ((size_t)b * NPTS + n) * KNBR;

    float mx[16];
#pragma unroll
    for (int i = 0; i < 16; ++i) mx[i] = -3.4e38f;

#pragma unroll
    for (int k = 0; k < KNBR; ++k) {
        int j = ip[k];
        const float4* ap = (const float4*)(g_A + ((size_t)b * NPTS + j) * COUT + g * 16);
#pragma unroll
        for (int q = 0; q < 4; ++q) {
            float4 v = ap[q];
            mx[q * 4 + 0] = fmaxf(mx[q * 4 + 0], v.x);
            mx[q * 4 + 1] = fmaxf(mx[q * 4 + 1], v.y);
            mx[q * 4 + 2] = fmaxf(mx[q * 4 + 2], v.z);
            mx[q * 4 + 3] = fmaxf(mx[q * 4 + 3], v.w);
        }
    }
    const float4* cp = (const float4*)(g_Cp + ((size_t)b * NPTS + n) * COUT + g * 16);
    float* op = out + ((size_t)b * COUT + g * 16) * NPTS + n;
#pragma unroll
    for (int q = 0; q < 4; ++q) {
        float4 c = cp[q];
        op[(q * 4 + 0) * NPTS] = fmaxf(c.x + mx[q * 4 + 0], 0.f);
        op[(q * 4 + 1) * NPTS] = fmaxf(c.y + mx[q * 4 + 1], 0.f);
        op[(q * 4 + 2) * NPTS] = fmaxf(c.z + mx[q * 4 + 2], 0.f);
        op[(q * 4 + 3) * NPTS] = fmaxf(c.w + mx[q * 4 + 3], 0.f);
    }
}

// ---------------- launch ----------------
extern "C" void kernel_launch(void* const* d_in, const int* in_sizes, int n_in,
                              void* d_out, int out_size) {
    const float *x = nullptr, *W1 = nullptr, *b1 = nullptr, *W2 = nullptr, *b2 = nullptr;
    for (int i = 0; i < n_in; ++i) {
        int s = in_sizes[i];
        const float* p = (const float*)d_in[i];
        if      (s == BATCH * CDIM * NPTS) x = p;
        else if (s == COUT * CDIM)        { if (!W1) W1 = p; else W2 = p; }
        else if (s == COUT)               { if (!b1) b1 = p; else b2 = p; }
    }
    float* out = (float*)d_out;
    (void)out_size;

    cudaFuncSetAttribute(knn_mma_kernel, cudaFuncAttributeMaxDynamicSharedMemorySize, KNN_SMEM);

    sq_kernel      <<<dim3(NPTS / 256, BATCH), 256>>>(x);
    tr_kernel      <<<dim3(NPTS / 32, CDIM / 32, BATCH), dim3(32, 8)>>>(x);
    knn_mma_kernel <<<dim3(NPTS / 128, BATCH), 256, KNN_SMEM>>>();
    rescore_kernel <<<dim3(NPTS / 4, BATCH), 128>>>();
    feat_kernel    <<<dim3(NPTS / 64, BATCH), 256>>>(x, W1, b1, W2, b2);
    gather_kernel  <<<dim3(NPTS / 64, BATCH), 256>>>(out);
}

// round 6
// speedup vs baseline: 1.5557x; 1.5557x over previous
#include <cuda_runtime.h>
#include <cuda_bf16.h>
#include <cstdint>

#define BATCH 8
#define CDIM  64
#define NPTS  4096
#define KNBR  16
#define COUT  64
#define KSUP  32          // approximate superset size per row
#define NC    128         // candidates per tile in phase B
#define NTIL  (NPTS / NC) // 32

typedef unsigned long long ull;

// ---------------- scratch (no allocations allowed) ----------------
__device__ float          g_sq  [BATCH * NPTS];
__device__ int            g_idx [BATCH * NPTS * KNBR];
__device__ float          g_A   [BATCH * NPTS * COUT];
__device__ float          g_Cp  [BATCH * NPTS * COUT];
__device__ float          g_xt  [BATCH * NPTS * CDIM];   // point-major fp32
__device__ __nv_bfloat16  g_xh  [BATCH * NPTS * CDIM];   // point-major bf16
__device__ short          g_cand[BATCH * NPTS * KSUP];

// ---------------- helpers ----------------
__device__ __forceinline__ uint32_t smem_u32(const void* p) {
    uint32_t a;
    asm("{ .reg .u64 t; cvta.to.shared.u64 t, %1; cvt.u32.u64 %0, t; }" : "=r"(a) : "l"(p));
    return a;
}
__device__ __forceinline__ unsigned fsort(float v) {
    unsigned u = __float_as_uint(v);
    return u ^ (0x80000000u | (unsigned)((int)u >> 31));
}
__device__ __forceinline__ float funsort(unsigned s) {
    unsigned u = (s & 0x80000000u) ? (s ^ 0x80000000u) : ~s;
    return __uint_as_float(u);
}
__device__ __forceinline__ void ldmx4(uint32_t* r, uint32_t addr) {
    asm volatile("ldmatrix.sync.aligned.m8n8.x4.shared.b16 {%0,%1,%2,%3}, [%4];"
                 : "=r"(r[0]), "=r"(r[1]), "=r"(r[2]), "=r"(r[3]) : "r"(addr));
}
__device__ __forceinline__ void mma16816(float* c, const uint32_t* a, uint32_t b0, uint32_t b1) {
    asm volatile("mma.sync.aligned.m16n8k16.row.col.f32.bf16.bf16.f32 "
                 "{%0,%1,%2,%3}, {%4,%5,%6,%7}, {%8,%9}, {%0,%1,%2,%3};"
                 : "+f"(c[0]), "+f"(c[1]), "+f"(c[2]), "+f"(c[3])
                 : "r"(a[0]), "r"(a[1]), "r"(a[2]), "r"(a[3]), "r"(b0), "r"(b1));
}
// swizzled byte offset of 16B granule g (0..7) in row rr of a [rows][64bf16] tile
__device__ __forceinline__ int swz(int rr, int g) {
    return rr * 128 + ((g ^ (rr & 7)) << 4);
}

// ---------------- kernel 1: squared norms (exact fp32) ----------------
__global__ void sq_kernel(const float* __restrict__ x) {
    int b = blockIdx.y;
    int n = blockIdx.x * blockDim.x + threadIdx.x;
    const float* xp = x + (size_t)b * CDIM * NPTS + n;
    float s = 0.f;
#pragma unroll
    for (int c = 0; c < CDIM; ++c) { float v = xp[c * NPTS]; s = fmaf(v, v, s); }
    g_sq[b * NPTS + n] = s;
}

// ---------------- kernel 1b: transpose to point-major fp32 + bf16 ----------------
__global__ void tr_kernel(const float* __restrict__ x) {
    __shared__ float tile[32][33];
    const int tx = threadIdx.x, ty = threadIdx.y;
    const int n0 = blockIdx.x * 32, c0 = blockIdx.y * 32, b = blockIdx.z;
    const float* xb = x + (size_t)b * CDIM * NPTS;
#pragma unroll
    for (int i = 0; i < 4; ++i)
        tile[ty + i * 8][tx] = xb[(c0 + ty + i * 8) * NPTS + n0 + tx];
    __syncthreads();
#pragma unroll
    for (int i = 0; i < 4; ++i) {
        int n = n0 + ty + i * 8, c = c0 + tx;
        float v = tile[tx][ty + i * 8];
        size_t o = ((size_t)b * NPTS + n) * CDIM + c;
        g_xt[o] = v;
        g_xh[o] = __float2bfloat16(v);
    }
}

// ---------------- kernel 2: HMMA approx distances + top-32 superset ----------------
#define PSTR   129                         // pending entries per row (ull), fits 128 worst-case
#define SM_A    0                          // 16384
#define SM_B0   16384                      // 16384
#define SM_B1   32768                      // 16384
#define SM_SQSL 49152                      // float[2][128] = 1024
#define SM_THR  (SM_SQSL + 1024)           // float[128]
#define SM_CNT  (SM_THR + 512)             // int[128]
#define SM_PEND (SM_CNT + 512)             // ull[128*129] = 132096
#define KNN_SMEM (SM_PEND + 128 * PSTR * 8)

__global__ __launch_bounds__(256) void knn_mma_kernel() {
    extern __shared__ char sm[];
    float* sqsl = (float*)(sm + SM_SQSL);
    float* thr  = (float*)(sm + SM_THR);
    int*   cnt  = (int*)  (sm + SM_CNT);
    ull*   pend = (ull*)  (sm + SM_PEND);

    const int tid  = threadIdx.x;
    const int w    = tid >> 5;
    const int lane = tid & 31;
    const int b    = blockIdx.y;
    const int row0 = blockIdx.x * 128;
    const uint32_t smb = smem_u32(sm);

    const __nv_bfloat16* gb = g_xh + (size_t)b * NPTS * CDIM;

    // prologue: A tile (swizzled), B tile 0, sq slice 0, thr/cnt
#pragma unroll
    for (int i = 0; i < 4; ++i) {
        int q = tid + i * 256, rr = q >> 3, g = q & 7;
        *(uint4*)(sm + SM_A + swz(rr, g))  = *(const uint4*)(gb + (size_t)(row0 + rr) * CDIM + g * 8);
        *(uint4*)(sm + SM_B0 + swz(rr, g)) = *(const uint4*)(gb + (size_t)rr * CDIM + g * 8);
    }
    if (tid < 32)  *(float4*)(sqsl + tid * 4) = *(const float4*)(g_sq + (size_t)b * NPTS + tid * 4);
    if (tid < 128) { thr[tid] = 3.4e38f; cnt[tid] = 0; }
    __syncthreads();

    // GEMM role (all 8 warps): rows wrow..wrow+15
    const int wrow = w * 16;
    const int arow = wrow + (lane & 7) + ((lane >> 3) & 1) * 8;
    const int rA   = wrow + (lane >> 2);
    const int rB   = rA + 8;

    // A fragments: block-constant, load once
    uint32_t af[4][4];
#pragma unroll
    for (int kc = 0; kc < 4; ++kc) {
        int ach = kc * 2 + (lane >> 4);
        ldmx4(af[kc], smb + SM_A + swz(arow, ach));
    }

    // selection role (threads 0..127): row = row0 + tid, top-32 in 32-bit split keys
    unsigned kv[KSUP], ki[KSUP];
    unsigned worst = 0xFFFFFFFFu; int wpos = 0;
#pragma unroll
    for (int s = 0; s < KSUP; ++s) { kv[s] = 0xFFFFFFFFu; ki[s] = 0xFFFFu; }

    for (int t = 0; t < NTIL; ++t) {
        const uint32_t bbase = smb + ((t & 1) ? SM_B1 : SM_B0);
        const float*   sql   = sqsl + (t & 1) * 128;
        const float thrA = thr[rA];
        const float thrB = thr[rB];
        const int   tb   = t * NC;

#pragma unroll
        for (int nf = 0; nf < 16; ++nf) {
            // B fragments for this n-slab (plain ldmatrix on [n][k] rows)
            int brow = nf * 8 + (lane & 7);
            int bg   = lane >> 3;
            uint32_t p[4], q4[4];
            ldmx4(p,  bbase + swz(brow, bg));
            ldmx4(q4, bbase + swz(brow, bg + 4));
            float acc[4] = {0.f, 0.f, 0.f, 0.f};
            mma16816(acc, af[0], p[0],  p[1]);
            mma16816(acc, af[1], p[2],  p[3]);
            mma16816(acc, af[2], q4[0], q4[1]);
            mma16816(acc, af[3], q4[2], q4[3]);

            // fused epilogue for this nf (acc liveness = 4)
            int   mloc = (lane & 3) * 2 + nf * 8;
            float s0 = sql[mloc], s1 = sql[mloc + 1];
            int   m0 = tb + mloc;
            float v00 = fmaf(-2.f, acc[0], s0);
            float v01 = fmaf(-2.f, acc[1], s1);
            float v10 = fmaf(-2.f, acc[2], s0);
            float v11 = fmaf(-2.f, acc[3], s1);
            if (v00 <= thrA) { int p0 = atomicAdd(&cnt[rA], 1);
                pend[rA * PSTR + p0] = ((ull)fsort(v00) << 32) | (unsigned)m0; }
            if (v01 <= thrA) { int p0 = atomicAdd(&cnt[rA], 1);
                pend[rA * PSTR + p0] = ((ull)fsort(v01) << 32) | (unsigned)(m0 + 1); }
            if (v10 <= thrB) { int p0 = atomicAdd(&cnt[rB], 1);
                pend[rB * PSTR + p0] = ((ull)fsort(v10) << 32) | (unsigned)m0; }
            if (v11 <= thrB) { int p0 = atomicAdd(&cnt[rB], 1);
                pend[rB * PSTR + p0] = ((ull)fsort(v11) << 32) | (unsigned)(m0 + 1); }
        }
        __syncthreads();   // appends visible to flush threads

        if (tid < 128) {
            // coherent per-row flush: thread tid owns row tid
            unsigned myc  = (unsigned)cnt[tid];
            unsigned cmax = __reduce_max_sync(0xffffffffu, myc);
            for (unsigned j = 0; j < cmax; ++j) {
                unsigned kvn = 0xFFFFFFFFu, kin = 0;
                if (j < myc) {
                    ull e = pend[tid * PSTR + j];
                    kvn = (unsigned)(e >> 32);
                    kin = (unsigned)e;
                }
                bool take = kvn < worst;
                if (__any_sync(0xffffffffu, take)) {
#pragma unroll
                    for (int s = 0; s < KSUP; ++s)
                        if (take && s == wpos) { kv[s] = kvn; ki[s] = kin; }
                    unsigned wv = kv[0]; int pp = 0;
#pragma unroll
                    for (int s = 1; s < KSUP; ++s)
                        if (kv[s] > wv) { wv = kv[s]; pp = s; }
                    worst = wv; wpos = pp;
                }
            }
            thr[tid] = (worst == 0xFFFFFFFFu) ? 3.4e38f : funsort(worst);
            cnt[tid] = 0;
        } else if (t + 1 < NTIL) {
            // warps 4-7: prefetch next B tile + sq slice
            char* dst = sm + (((t + 1) & 1) ? SM_B1 : SM_B0);
            const __nv_bfloat16* src = gb + (size_t)(t + 1) * NC * CDIM;
            int t2 = tid - 128;
#pragma unroll
            for (int i = 0; i < 8; ++i) {
                int q = t2 + i * 128, rr = q >> 3, g = q & 7;
                *(uint4*)(dst + swz(rr, g)) = *(const uint4*)(src + (size_t)rr * CDIM + g * 8);
            }
            if (t2 < 32)
                *(float4*)(sqsl + ((t + 1) & 1) * 128 + t2 * 4) =
                    *(const float4*)(g_sq + (size_t)b * NPTS + (t + 1) * NC + t2 * 4);
        }
        __syncthreads();
    }

    if (tid < 128) {
        short* op = g_cand + ((size_t)b * NPTS + row0 + tid) * KSUP;
#pragma unroll
        for (int k = 0; k < KSUP; ++k) op[k] = (short)ki[k];
    }
}

// ---------------- kernel 2b: exact rescore of 32 candidates, top-16 ----------------
__global__ __launch_bounds__(256) void rescore_kernel() {
    __shared__ float xrow[8][CDIM];
    const int lane = threadIdx.x & 31;
    const int w    = threadIdx.x >> 5;
    const int b    = blockIdx.y;
    const int n    = blockIdx.x * 8 + w;
    const size_t rb = (size_t)b * NPTS + n;

    // stage own row
    *(float2*)(&xrow[w][lane * 2]) = *(const float2*)(g_xt + rb * CDIM + lane * 2);
    __syncwarp();

    int j = (int)g_cand[rb * KSUP + lane];
    ull key;
    if (j == n) {
        key = ~0ULL;
    } else {
        const float* yp = g_xt + ((size_t)b * NPTS + j) * CDIM;
        float dot = 0.f;
#pragma unroll
        for (int c = 0; c < CDIM / 4; ++c) {
            float4 yv = *(const float4*)(yp + c * 4);
            float4 xv = *(const float4*)(&xrow[w][c * 4]);
            dot = fmaf(xv.x, yv.x, dot);
            dot = fmaf(xv.y, yv.y, dot);
            dot = fmaf(xv.z, yv.z, dot);
            dot = fmaf(xv.w, yv.w, dot);
        }
        float dist = fmaf(-2.f, dot, g_sq[(size_t)b * NPTS + j]);
        key = ((ull)fsort(dist) << 32) | (unsigned)j;
    }
    // 32-lane bitonic sort (ascending)
#pragma unroll
    for (int k = 2; k <= 32; k <<= 1) {
#pragma unroll
        for (int jj = k >> 1; jj > 0; jj >>= 1) {
            ull other = __shfl_xor_sync(0xffffffffu, key, jj);
            bool up   = ((lane & k) == 0);
            bool low  = ((lane & jj) == 0);
            bool keep_small = (low == up);
            ull mn = key < other ? key : other;
            ull mx = key < other ? other : key;
            key = keep_small ? mn : mx;
        }
    }
    if (lane < KNBR)
        g_idx[rb * KNBR + lane] = (int)(key & 0xFFFFu);
}

// ---------------- kernel 3: A = W1.x ; Cpre = (W2-W1).x + b1+b2 ----------------
__global__ void feat_kernel(const float* __restrict__ x,
                            const float* __restrict__ W1, const float* __restrict__ b1,
                            const float* __restrict__ W2, const float* __restrict__ b2) {
    __shared__ float xs [CDIM][64];
    __shared__ float w1s[COUT][CDIM];
    __shared__ float wds[COUT][CDIM];
    __shared__ float bs [COUT];

    const int tid = threadIdx.x;
    const int b   = blockIdx.y;
    const int n0  = blockIdx.x * 64;
    const float* xb = x + (size_t)b * CDIM * NPTS;

#pragma unroll
    for (int i = 0; i < 4; ++i) {
        int q = tid + i * 256, c = q >> 4, mg = q & 15;
        *(float4*)(&xs[c][mg * 4]) = *(const float4*)(xb + c * NPTS + n0 + mg * 4);
    }
#pragma unroll
    for (int i = 0; i < 4; ++i) {
        int q = tid + i * 256, o = q >> 4, cg = (q & 15) * 4;
        float4 w1v = *(const float4*)(W1 + o * CDIM + cg);
        float4 w2v = *(const float4*)(W2 + o * CDIM + cg);
        *(float4*)(&w1s[o][cg]) = w1v;
        *(float4*)(&wds[o][cg]) = make_float4(w2v.x - w1v.x, w2v.y - w1v.y,
                                              w2v.z - w1v.z, w2v.w - w1v.w);
    }
    if (tid < COUT) bs[tid] = b1[tid] + b2[tid];
    __syncthreads();

    const int tx = tid & 15;
    const int ty = tid >> 4;
    float aA[4][4] = {}, aC[4][4] = {};
#pragma unroll 16
    for (int c = 0; c < CDIM; ++c) {
        float4 xv = *(const float4*)(&xs[c][tx * 4]);
        float xr[4] = { xv.x, xv.y, xv.z, xv.w };
#pragma unroll
        for (int jj = 0; jj < 4; ++jj) {
            float w1e = w1s[ty * 4 + jj][c];
            float wde = wds[ty * 4 + jj][c];
#pragma unroll
            for (int i = 0; i < 4; ++i) {
                aA[i][jj] = fmaf(xr[i], w1e, aA[i][jj]);
                aC[i][jj] = fmaf(xr[i], wde, aC[i][jj]);
            }
        }
    }
#pragma unroll
    for (int i = 0; i < 4; ++i) {
        int n = n0 + tx * 4 + i;
        float* ap = g_A  + ((size_t)b * NPTS + n) * COUT + ty * 4;
        float* cp = g_Cp + ((size_t)b * NPTS + n) * COUT + ty * 4;
        *(float4*)ap = make_float4(aA[i][0], aA[i][1], aA[i][2], aA[i][3]);
        *(float4*)cp = make_float4(aC[i][0] + bs[ty * 4 + 0],
                                   aC[i][1] + bs[ty * 4 + 1],
                                   aC[i][2] + bs[ty * 4 + 2],
                                   aC[i][3] + bs[ty * 4 + 3]);
    }
}

// ---------------- kernel 4: gather-max + relu (2 points/thread ILP) ----------------
__global__ __launch_bounds__(256) void gather_kernel(float* __restrict__ out) {
    const int tid = threadIdx.x;
    const int b   = blockIdx.y;
    const int l   = tid & 63;
    const int g   = tid >> 6;
    const int n1  = blockIdx.x * 128 + l;
    const int n2  = n1 + 64;
    const int* ip1 = g_idx + ((size_t)b * NPTS + n1) * KNBR;
    const int* ip2 = g_idx + ((size_t)b * NPTS + n2) * KNBR;

    float mx1[16], mx2[16];
#pragma unroll
    for (int i = 0; i < 16; ++i) { mx1[i] = -3.4e38f; mx2[i] = -3.4e38f; }

#pragma unroll
    for (int k = 0; k < KNBR; ++k) {
        int j1 = ip1[k], j2 = ip2[k];
        const float4* ap1 = (const float4*)(g_A + ((size_t)b * NPTS + j1) * COUT + g * 16);
        const float4* ap2 = (const float4*)(g_A + ((size_t)b * NPTS + j2) * COUT + g * 16);
#pragma unroll
        for (int q = 0; q < 4; ++q) {
            float4 v1 = ap1[q];
            float4 v2 = ap2[q];
            mx1[q * 4 + 0] = fmaxf(mx1[q * 4 + 0], v1.x);
            mx1[q * 4 + 1] = fmaxf(mx1[q * 4 + 1], v1.y);
            mx1[q * 4 + 2] = fmaxf(mx1[q * 4 + 2], v1.z);
            mx1[q * 4 + 3] = fmaxf(mx1[q * 4 + 3], v1.w);
            mx2[q * 4 + 0] = fmaxf(mx2[q * 4 + 0], v2.x);
            mx2[q * 4 + 1] = fmaxf(mx2[q * 4 + 1], v2.y);
            mx2[q * 4 + 2] = fmaxf(mx2[q * 4 + 2], v2.z);
            mx2[q * 4 + 3] = fmaxf(mx2[q * 4 + 3], v2.w);
        }
    }
    const float4* cp1 = (const float4*)(g_Cp + ((size_t)b * NPTS + n1) * COUT + g * 16);
    const float4* cp2 = (const float4*)(g_Cp + ((size_t)b * NPTS + n2) * COUT + g * 16);
    float* op1 = out + ((size_t)b * COUT + g * 16) * NPTS + n1;
    float* op2 = out + ((size_t)b * COUT + g * 16) * NPTS + n2;
#pragma unroll
    for (int q = 0; q < 4; ++q) {
        float4 c1 = cp1[q];
        float4 c2 = cp2[q];
        op1[(q * 4 + 0) * NPTS] = fmaxf(c1.x + mx1[q * 4 + 0], 0.f);
        op1[(q * 4 + 1) * NPTS] = fmaxf(c1.y + mx1[q * 4 + 1], 0.f);
        op1[(q * 4 + 2) * NPTS] = fmaxf(c1.z + mx1[q * 4 + 2], 0.f);
        op1[(q * 4 + 3) * NPTS] = fmaxf(c1.w + mx1[q * 4 + 3], 0.f);
        op2[(q * 4 + 0) * NPTS] = fmaxf(c2.x + mx2[q * 4 + 0], 0.f);
        op2[(q * 4 + 1) * NPTS] = fmaxf(c2.y + mx2[q * 4 + 1], 0.f);
        op2[(q * 4 + 2) * NPTS] = fmaxf(c2.z + mx2[q * 4 + 2], 0.f);
        op2[(q * 4 + 3) * NPTS] = fmaxf(c2.w + mx2[q * 4 + 3], 0.f);
    }
}

// ---------------- launch ----------------
extern "C" void kernel_launch(void* const* d_in, const int* in_sizes, int n_in,
                              void* d_out, int out_size) {
    const float *x = nullptr, *W1 = nullptr, *b1 = nullptr, *W2 = nullptr, *b2 = nullptr;
    for (int i = 0; i < n_in; ++i) {
        int s = in_sizes[i];
        const float* p = (const float*)d_in[i];
        if      (s == BATCH * CDIM * NPTS) x = p;
        else if (s == COUT * CDIM)        { if (!W1) W1 = p; else W2 = p; }
        else if (s == COUT)               { if (!b1) b1 = p; else b2 = p; }
    }
    float* out = (float*)d_out;
    (void)out_size;

    cudaFuncSetAttribute(knn_mma_kernel, cudaFuncAttributeMaxDynamicSharedMemorySize, KNN_SMEM);

    sq_kernel      <<<dim3(NPTS / 256, BATCH), 256>>>(x);
    tr_kernel      <<<dim3(NPTS / 32, CDIM / 32, BATCH), dim3(32, 8)>>>(x);
    knn_mma_kernel <<<dim3(NPTS / 128, BATCH), 256, KNN_SMEM>>>();
    rescore_kernel <<<dim3(NPTS / 8, BATCH), 256>>>();
    feat_kernel    <<<dim3(NPTS / 64, BATCH), 256>>>(x, W1, b1, W2, b2);
    gather_kernel  <<<dim3(NPTS / 128, BATCH), 256>>>(out);
}